// round 17
// baseline (speedup 1.0000x reference)
#include <cuda_runtime.h>
#include <cuda_fp16.h>
#include <cstdint>

// ---------------------------------------------------------------------------
// BiLSTM: B=32, T=512, D=512, H=512. out = [B,T,2H] fp32.
// FUSED persistent kernel, 148 CTAs x 512 threads:
//   Phase A: all CTAs project s-blocks q<20 (both dirs) via tf32 mma.
//   Phase B: CTAs 0-63 scan (32/dir, j-tile 16); CTAs 64-147 stream proj.
// R17 (= R16 + alignment fix): scan warps kw(4) x wm(4); ALL W fragments
//   register-hoisted (32 regs, ldmatrix once) -> mainloop is pure LDG+HMMA,
//   zero operand LDS. B frags streamed from g_hfrag (R15 layout). 4-way K
//   reduction via stride-34 PR slab (float2-aligned) + block bars.
// ---------------------------------------------------------------------------

#define B_  32
#define T_  512
#define D_  512
#define H_  512
#define G4  2048
#define NSCAN 64          // scan CTAs (32 per dir)
#define ARRV  256         // arrivals per dir per step (8 cell warps x 32 CTAs)
#define JT    16          // j columns per scan CTA
#define SHW  520          // W smem row stride (fp16)
#define PRS  34           // PR row stride (floats, even -> float2 aligned)
#define QA   20           // phase-A s-block prefix
#define NQ   128

// Scratch (device globals: allocation-free rule)
__device__ float g_xg[2][T_][G4][B_];        // [dir][t][gate*H+j][b]
__device__ uint2 g_hfrag[2][2][32][4][32];   // [buf][dir][ks][wn][lane] B-frag
__device__ unsigned g_bar2[2];
__device__ unsigned g_ctrA, g_ctrB;
__device__ unsigned g_done[NQ];

// ---------------------------------------------------------------------------
__device__ __forceinline__ uint32_t f2tf32(float f) {
    uint32_t r;
    asm("cvt.rna.tf32.f32 %0, %1;" : "=r"(r) : "f"(f));
    return r;
}
__device__ __forceinline__ void mma_tf32(float* c, const uint32_t* a, const uint32_t* b) {
    asm volatile(
        "mma.sync.aligned.m16n8k8.row.col.f32.tf32.tf32.f32 "
        "{%0,%1,%2,%3}, {%4,%5,%6,%7}, {%8,%9}, {%0,%1,%2,%3};"
        : "+f"(c[0]), "+f"(c[1]), "+f"(c[2]), "+f"(c[3])
        : "r"(a[0]), "r"(a[1]), "r"(a[2]), "r"(a[3]), "r"(b[0]), "r"(b[1]));
}
__device__ __forceinline__ void mma_f16(float* c, const uint32_t* a, const uint32_t* b) {
    asm volatile(
        "mma.sync.aligned.m16n8k16.row.col.f32.f16.f16.f32 "
        "{%0,%1,%2,%3}, {%4,%5,%6,%7}, {%8,%9}, {%0,%1,%2,%3};"
        : "+f"(c[0]), "+f"(c[1]), "+f"(c[2]), "+f"(c[3])
        : "r"(a[0]), "r"(a[1]), "r"(a[2]), "r"(a[3]), "r"(b[0]), "r"(b[1]));
}
__device__ __forceinline__ void ldmx4(uint32_t* r, uint32_t addr) {
    asm volatile("ldmatrix.sync.aligned.m8n8.x4.shared.b16 {%0,%1,%2,%3}, [%4];"
        : "=r"(r[0]), "=r"(r[1]), "=r"(r[2]), "=r"(r[3]) : "r"(addr));
}
__device__ __forceinline__ uint32_t smem_u32(const void* p) {
    uint32_t a;
    asm("{ .reg .u64 t; cvta.to.shared.u64 t, %1; cvt.u32.u64 %0, t; }"
        : "=r"(a) : "l"(p));
    return a;
}
__device__ __forceinline__ uint16_t hfu(__half v) { return __half_as_ushort(v); }
__device__ __forceinline__ void cell_bar() {
    asm volatile("bar.sync 12, 256;" ::: "memory");
}
__device__ __forceinline__ void block_bar() {
    asm volatile("bar.sync 0, 512;" ::: "memory");
}
__device__ __forceinline__ unsigned ld_acq(const unsigned* p) {
    unsigned v;
    asm volatile("ld.acquire.gpu.u32 %0, [%1];" : "=r"(v) : "l"(p) : "memory");
    return v;
}
__device__ __forceinline__ void red_rel(unsigned* p, unsigned v) {
    asm volatile("red.add.release.gpu.u32 [%0], %1;" :: "l"(p), "r"(v) : "memory");
}

// fast activations (validated R4/R6-R15)
__device__ __forceinline__ float sigf(float x) {
    return __fdividef(1.f, 1.f + __expf(-x));
}
__device__ __forceinline__ float tanhfast(float x) {
    float ax = fabsf(x);
    float e  = __expf(-2.f * ax);
    float t  = __fdividef(1.f - e, 1.f + e);
    return copysignf(t, x);
}

// ---------------------------------------------------------------------------
// init: zero h frag buffers, counters, flags
// ---------------------------------------------------------------------------
__global__ void init_kernel() {
    int idx = blockIdx.x * blockDim.x + threadIdx.x;
    if (idx < 2) g_bar2[idx] = 0u;
    if (idx == 2) g_ctrA = 0u;
    if (idx == 3) g_ctrB = 0u;
    if (idx >= 4 && idx < 4 + NQ) g_done[idx - 4] = 0u;
    uint2* z = &g_hfrag[0][0][0][0][0];      // 16384 uint2
    if (idx < 16384) z[idx] = make_uint2(0, 0);
}

// ---------------------------------------------------------------------------
// smem layout (bytes). W0 region reused by proj tiles AND by PR (all
// temporally disjoint: proj phase / W-frag init / steady-state steps).
// ---------------------------------------------------------------------------
#define PA_OFF 0                 // proj A_s: 32*136 floats = 17408
#define PB_OFF 17408             // proj B_s: 17408
#define W0_OFF 0                 // scan W staging: 64*SHW*2 = 66560
#define PR_OFF 0                 // PR slab: 4*64*PRS*4 = 34816 (reuses W0)
#define HN2_OFF 66560            // half [16 j][34] = 1088 -> pad 1152
#define HNF_OFF 67712            // float [16 j][34] = 2176
#define BC_OFF 69888             // broadcast slot
#define SMEM_TOT 70016

#define SSTR 136
#define KCH  32

// ---------------------------------------------------------------------------
// proj tile (512 threads): 128x128 tf32 tile; 16 warps = 4 mw x 4 nw.
// (validated R12-R15)
// ---------------------------------------------------------------------------
__device__ void proj_tile(char* sm, int xtile, int mtile,
    const float* __restrict__ x,
    const float* __restrict__ Wf, const float* __restrict__ Wb,
    const float* __restrict__ bihf, const float* __restrict__ bhhf,
    const float* __restrict__ bihb, const float* __restrict__ bhhb)
{
    float* A_s = (float*)(sm + PA_OFF);
    float* B_s = (float*)(sm + PB_OFF);

    const int tid  = threadIdx.x;
    const int lane = tid & 31;
    const int wid  = tid >> 5;
    const int mw   = wid & 3;
    const int nw   = wid >> 2;

    const int dir  = mtile >> 4;
    const int mg0  = (mtile & 15) * 128;
    const int t0   = xtile * 4;
    const float* W = dir ? Wb : Wf;

    const int lrow = tid >> 2;
    const int ls2  = (tid & 3) * 2;
    const int bL   = lrow & 31;
    const int dtL  = lrow >> 5;
    const float* Arow = W + (size_t)(mg0 + lrow) * D_;
    const float* Brow = x + ((size_t)bL * T_ + t0 + dtL) * D_;

    float acc[2][4][4];
#pragma unroll
    for (int mi = 0; mi < 2; mi++)
#pragma unroll
        for (int ni = 0; ni < 4; ni++)
#pragma unroll
            for (int q = 0; q < 4; q++) acc[mi][ni][q] = 0.f;

    const int frag_k = lane & 3;
    const int frag_r = lane >> 2;

    for (int c = 0; c < D_ / KCH; c++) {
        const int kc = c * KCH;
#pragma unroll
        for (int it = 0; it < 2; it++) {
            int k0 = (ls2 + it) * 4;
            float4 av = *(const float4*)(Arow + kc + k0);
            float4 bv = *(const float4*)(Brow + kc + k0);
            A_s[(k0 + 0) * SSTR + lrow] = __uint_as_float(f2tf32(av.x));
            A_s[(k0 + 1) * SSTR + lrow] = __uint_as_float(f2tf32(av.y));
            A_s[(k0 + 2) * SSTR + lrow] = __uint_as_float(f2tf32(av.z));
            A_s[(k0 + 3) * SSTR + lrow] = __uint_as_float(f2tf32(av.w));
            B_s[(k0 + 0) * SSTR + lrow] = __uint_as_float(f2tf32(bv.x));
            B_s[(k0 + 1) * SSTR + lrow] = __uint_as_float(f2tf32(bv.y));
            B_s[(k0 + 2) * SSTR + lrow] = __uint_as_float(f2tf32(bv.z));
            B_s[(k0 + 3) * SSTR + lrow] = __uint_as_float(f2tf32(bv.w));
        }
        __syncthreads();

#pragma unroll
        for (int ks = 0; ks < KCH / 8; ks++) {
            const int kb = ks * 8 + frag_k;
            uint32_t afr[2][4], bfr[4][2];
#pragma unroll
            for (int mi = 0; mi < 2; mi++) {
                int m = mw * 32 + mi * 16 + frag_r;
                afr[mi][0] = __float_as_uint(A_s[kb * SSTR + m]);
                afr[mi][1] = __float_as_uint(A_s[kb * SSTR + m + 8]);
                afr[mi][2] = __float_as_uint(A_s[(kb + 4) * SSTR + m]);
                afr[mi][3] = __float_as_uint(A_s[(kb + 4) * SSTR + m + 8]);
            }
#pragma unroll
            for (int ni = 0; ni < 4; ni++) {
                int n = nw * 32 + ni * 8 + frag_r;
                bfr[ni][0] = __float_as_uint(B_s[kb * SSTR + n]);
                bfr[ni][1] = __float_as_uint(B_s[(kb + 4) * SSTR + n]);
            }
#pragma unroll
            for (int mi = 0; mi < 2; mi++)
#pragma unroll
                for (int ni = 0; ni < 4; ni++)
                    mma_tf32(acc[mi][ni], afr[mi], bfr[ni]);
        }
        __syncthreads();
    }

    const int t  = t0 + nw;
    const int bc = 2 * (lane & 3);
#pragma unroll
    for (int mi = 0; mi < 2; mi++) {
        int g0 = mg0 + mw * 32 + mi * 16 + frag_r;
        float bias0 = dir ? (bihb[g0] + bhhb[g0]) : (bihf[g0] + bhhf[g0]);
        float bias1 = dir ? (bihb[g0 + 8] + bhhb[g0 + 8]) : (bihf[g0 + 8] + bhhf[g0 + 8]);
#pragma unroll
        for (int ni = 0; ni < 4; ni++) {
            int b = ni * 8 + bc;
            *(float2*)&g_xg[dir][t][g0][b] =
                make_float2(acc[mi][ni][0] + bias0, acc[mi][ni][1] + bias0);
            *(float2*)&g_xg[dir][t][g0 + 8][b] =
                make_float2(acc[mi][ni][2] + bias1, acc[mi][ni][3] + bias1);
        }
    }
}

// ---------------------------------------------------------------------------
// fused persistent kernel
// ---------------------------------------------------------------------------
__global__ __launch_bounds__(512, 1) void fused_kernel(
    const float* __restrict__ x,
    const int*   __restrict__ lengths,
    const float* __restrict__ Wihf, const float* __restrict__ Whhf,
    const float* __restrict__ bihf, const float* __restrict__ bhhf,
    const float* __restrict__ Wihb, const float* __restrict__ Whhb,
    const float* __restrict__ bihb, const float* __restrict__ bhhb,
    float*       __restrict__ out)
{
    extern __shared__ __align__(16) char sm[];
    int* bcst = (int*)(sm + BC_OFF);
    const int tid  = threadIdx.x;
    const int lane = tid & 31;
    const int wq   = tid >> 5;

    // ================= Phase A: all CTAs project s-blocks q < QA ==========
    for (;;) {
        if (tid == 0) *bcst = (int)atomicAdd(&g_ctrA, 1u);
        __syncthreads();
        int idx = *bcst;
        __syncthreads();
        if (idx >= QA * 32) break;
        int q = idx >> 5, i = idx & 31;
        proj_tile(sm, (i < 16) ? q : (127 - q), i,
                  x, Wihf, Wihb, bihf, bhhf, bihb, bhhb);
        __threadfence();
        __syncthreads();
        if (tid == 0) atomicAdd(&g_done[q], 1u);
    }

    // ================= Phase B workers: remaining proj tiles ==============
    if (blockIdx.x >= NSCAN) {
        for (;;) {
            if (tid == 0) *bcst = (int)atomicAdd(&g_ctrB, 1u);
            __syncthreads();
            int idx = *bcst;
            __syncthreads();
            if (idx >= (NQ - QA) * 32) return;
            int q = QA + (idx >> 5), i = idx & 31;
            proj_tile(sm, (i < 16) ? q : (127 - q), i,
                      x, Wihf, Wihb, bihf, bhhf, bihb, bhhb);
            __threadfence();
            __syncthreads();
            if (tid == 0) atomicAdd(&g_done[q], 1u);
        }
    }

    // ================= Scan CTAs (0..63): 32 per dir, j-tile 16 ===========
    __half* W0_s  = (__half*)(sm + W0_OFF);   // transient (A-frag init only)
    float*  PR_s  = (float*)(sm + PR_OFF);    // [4 kw][64 row][PRS] (reuses W0)
    __half* HN2_s = (__half*)(sm + HN2_OFF);  // [16 j][34]
    float*  HNF_s = (float*)(sm + HNF_OFF);   // [16 j][34]

    const int bx  = blockIdx.x;
    const int dir = bx >> 5;
    const int j0  = (bx & 31) * JT;
    const int ksb = j0 >> 4;                  // this CTA's ks block
    const float* W = dir ? Whhb : Whhf;
    unsigned* bar = &g_bar2[dir];

    __syncthreads();   // phase A used smem

    // ---- stage W fp16, gate-interleaved rows (same formula as R15):
    //   jhalf = mrow>>5 ; gate = ((mrow>>4)&1)*2 + ((mrow>>3)&1) ; jl = mrow&7
#pragma unroll
    for (int i = 0; i < 16; i++) {
        int v = tid + i * 512;              // 0..8191 (64 rows x 128 segs)
        int mrow = v >> 7;
        int seg  = v & 127;
        int jhalf = mrow >> 5;
        int gate = ((mrow >> 4) & 1) * 2 + ((mrow >> 3) & 1);
        int jl   = mrow & 7;
        float4 wv = __ldg((const float4*)(W +
            (size_t)((gate << 9) + j0 + jhalf * 8 + jl) * D_) + seg);
        uint32_t pA = (uint32_t)hfu(__float2half_rn(wv.x)) |
                      ((uint32_t)hfu(__float2half_rn(wv.y)) << 16);
        uint32_t pB = (uint32_t)hfu(__float2half_rn(wv.z)) |
                      ((uint32_t)hfu(__float2half_rn(wv.w)) << 16);
        *(uint2*)((char*)W0_s + (mrow * SHW + seg * 4) * 2) = make_uint2(pA, pB);
    }
    __syncthreads();

    // warp decomposition: kw(4) x wm(4); each warp covers all 4 n-tiles
    const int kw = wq & 3;
    const int wm = wq >> 2;                 // m16 tile (16 rows)
    const int l8 = lane & 7, sel = lane >> 3;
    const uint32_t w0b = smem_u32(W0_s);
    const uint32_t aoff = w0b +
        (uint32_t)((wm * 16 + ((sel & 1) ? 8 : 0) + l8) * SHW
                   + ((sel >> 1) ? 8 : 0) + kw * 128) * 2;

    // ---- hoist ALL A fragments: 8 ks x 4 regs = 32 regs (time-invariant) ----
    uint32_t a0h[8][4];
#pragma unroll
    for (int ks = 0; ks < 8; ks++)
        ldmx4(a0h[ks], aoff + ks * 32);
    __syncthreads();                         // W0_s dead; PR slab reuses it

    // consumer B-frag base: g_hfrag[cur][dir][kw*8 + ks][wn][lane]
    const uint2* hf0 = &g_hfrag[0][dir][0][0][lane];
    const uint2* hf1 = &g_hfrag[1][dir][0][0][lane];

    // producer store: flat uint32 index ksb*256 + tid (cell threads tid<256)
    uint32_t* hp0 = (uint32_t*)&g_hfrag[0][dir][0][0][0] + ksb * 256 + tid;
    uint32_t* hp1 = (uint32_t*)&g_hfrag[1][dir][0][0][0] + ksb * 256 + tid;
    // producer gather from HN2 (R15-validated mapping)
    const int pk1 = ((tid >> 1) & 3) * 2 + (tid & 1) * 8;
    const int pb  = ((tid >> 6) & 3) * 8 + (((tid >> 1) & 31) >> 2);

    // cell identity (tid < 256): thread u -> j = j0 + (u>>4), b pair = (u&15)*2
    const bool is_cell = (tid < 256);
    const int jl_c = tid >> 4;               // 0..15 (valid for cells)
    const int jj   = j0 + jl_c;
    const int b0   = (tid & 15) * 2;
    const int jh_c = jl_c >> 3, jr_c = jl_c & 7;
    const int lenA = __ldg(&lengths[b0 & 31]);
    const int lenB = __ldg(&lengths[(b0 + 1) & 31]);
    float cA = 0.f, hA = 0.f, cB = 0.f, hB = 0.f;
    int cur = 0;
    unsigned target = 0;

    for (int s = 0; s < T_; s++) {
        const int t = dir ? (T_ - 1 - s) : s;

        // ---- xg gate + prefetch (cell threads) ----
        float2 xi2, xf2, xg2, xo2;
        if (is_cell) {
            if ((s & 3) == 0) {
                const unsigned q = (unsigned)(s >> 2);
                while (ld_acq(&g_done[q]) < 32u) { }
            }
            const float* xgp = &g_xg[dir][t][0][0];
            xi2 = *(const float2*)(xgp + (((0 << 9) + jj) << 5) + b0);
            xf2 = *(const float2*)(xgp + (((1 << 9) + jj) << 5) + b0);
            xg2 = *(const float2*)(xgp + (((2 << 9) + jj) << 5) + b0);
            xo2 = *(const float2*)(xgp + (((3 << 9) + jj) << 5) + b0);
        }

        // ---- per-warp wait: all h(s-1) frag stores released ----
        while (ld_acq(bar) < target) { }

        const uint2* hfb = cur ? hf1 : hf0;

        // ---- mainloop: 8 k16-steps x 4 n-tiles; A in regs, B via LDG,
        //      streamed in 2-ks windows with prefetch distance 2 ----
        float c[4][4];
#pragma unroll
        for (int ni = 0; ni < 4; ni++)
#pragma unroll
            for (int q = 0; q < 4; q++) c[ni][q] = 0.f;

        uint2 bw[2][8];                      // [buf][ks2*4+wn]
#pragma unroll
        for (int p = 0; p < 2; p++)
#pragma unroll
            for (int ks2 = 0; ks2 < 2; ks2++)
#pragma unroll
                for (int wn = 0; wn < 4; wn++)
                    bw[p][ks2 * 4 + wn] =
                        __ldcg(hfb + (((kw * 8 + p * 2 + ks2) << 7) + (wn << 5)));
#pragma unroll
        for (int p = 0; p < 4; p++) {
#pragma unroll
            for (int ks2 = 0; ks2 < 2; ks2++) {
                const int ks = p * 2 + ks2;
#pragma unroll
                for (int wn = 0; wn < 4; wn++)
                    mma_f16(c[wn], a0h[ks], (const uint32_t*)&bw[p & 1][ks2 * 4 + wn]);
            }
            if (p < 2) {
#pragma unroll
                for (int ks2 = 0; ks2 < 2; ks2++)
#pragma unroll
                    for (int wn = 0; wn < 4; wn++)
                        bw[p & 1][ks2 * 4 + wn] =
                            __ldcg(hfb + (((kw * 8 + (p + 2) * 2 + ks2) << 7) + (wn << 5)));
            }
        }

        // ---- write partial C -> PR[kw][row][PRS], rows wm*16 + {fr, fr+8} ----
        {
            int fr = lane >> 2, fc2 = (lane & 3) * 2;
            float* Pk = PR_s + kw * (64 * PRS);
#pragma unroll
            for (int wn = 0; wn < 4; wn++) {
                *(float2*)&Pk[(wm * 16 + fr) * PRS + wn * 8 + fc2] =
                    make_float2(c[wn][0], c[wn][1]);
                *(float2*)&Pk[(wm * 16 + fr + 8) * PRS + wn * 8 + fc2] =
                    make_float2(c[wn][2], c[wn][3]);
            }
        }
        block_bar();                         // PR complete

        if (is_cell) {
            // ---- gather 4 gates x 4 kw partials: row(g) formula = staging ----
            float gsum[4][2];
#pragma unroll
            for (int g = 0; g < 4; g++) {
                int row = (jh_c * 2 + (g >> 1)) * 16 + (g & 1) * 8 + jr_c;
                float2 acc2 = make_float2(0.f, 0.f);
#pragma unroll
                for (int k2 = 0; k2 < 4; k2++) {
                    float2 v = *(const float2*)&PR_s[k2 * (64 * PRS) + row * PRS + b0];
                    acc2.x += v.x; acc2.y += v.y;
                }
                gsum[g][0] = acc2.x; gsum[g][1] = acc2.y;
            }

            // ---- LSTM cells in registers ----
            {
                float ig = sigf(gsum[0][0] + xi2.x), fg = sigf(gsum[1][0] + xf2.x);
                float gg = tanhfast(gsum[2][0] + xg2.x), og = sigf(gsum[3][0] + xo2.x);
                float cn = fg * cA + ig * gg;
                float hn = og * tanhfast(cn);
                if (t < lenA) { cA = cn; hA = hn; }
            }
            {
                float ig = sigf(gsum[0][1] + xi2.y), fg = sigf(gsum[1][1] + xf2.y);
                float gg = tanhfast(gsum[2][1] + xg2.y), og = sigf(gsum[3][1] + xo2.y);
                float cn = fg * cB + ig * gg;
                float hn = og * tanhfast(cn);
                if (t < lenB) { cB = cn; hB = hn; }
            }

            // ---- publish: HN2 (frag gather) + HNF (out tile) ----
            __half2 hh = __floats2half2_rn(hA, hB);
            *(__half2*)&HN2_s[jl_c * 34 + b0] = hh;
            *(float2*)&HNF_s[jl_c * 34 + b0] = make_float2(hA, hB);
            cell_bar();                      // HN2 complete (256 threads)

            // ---- frag-image store: ONE uint32/thread, coalesced 1KB ----
            uint32_t w = (uint32_t)hfu(HN2_s[pk1 * 34 + pb]) |
                         ((uint32_t)hfu(HN2_s[(pk1 + 1) * 34 + pb]) << 16);
            uint32_t* hp = cur ? hp0 : hp1;  // write NEXT buffer
            asm volatile("st.global.cg.u32 [%0], %1;" :: "l"(hp), "r"(w) : "memory");
            __syncwarp();
            if (lane == 0) red_rel(bar, 1u); // release h(s) frags
        }

        block_bar();                         // HNF ready; PR reusable next step
        if (!is_cell) {
            int u2 = tid - 256;              // 0..255
            int bb = u2 >> 3, jp = (u2 & 7) * 2;
            float2 v = make_float2(HNF_s[jp * 34 + bb], HNF_s[(jp + 1) * 34 + bb]);
            *(float2*)&out[((size_t)bb * T_ + t) * (2 * H_) + (dir << 9) + j0 + jp] = v;
        }

        target += ARRV;
        cur ^= 1;
    }
}

// ---------------------------------------------------------------------------
extern "C" void kernel_launch(void* const* d_in, const int* in_sizes, int n_in,
                              void* d_out, int out_size)
{
    const float* x      = (const float*)d_in[0];
    const int*   lens   = (const int*)  d_in[1];
    const float* Wihf   = (const float*)d_in[2];
    const float* Whhf   = (const float*)d_in[3];
    const float* bihf   = (const float*)d_in[4];
    const float* bhhf   = (const float*)d_in[5];
    const float* Wihb   = (const float*)d_in[6];
    const float* Whhb   = (const float*)d_in[7];
    const float* bihb   = (const float*)d_in[8];
    const float* bhhb   = (const float*)d_in[9];
    float* out = (float*)d_out;

    cudaFuncSetAttribute(fused_kernel,
                         cudaFuncAttributeMaxDynamicSharedMemorySize, SMEM_TOT);

    init_kernel<<<256, 256>>>();

    fused_kernel<<<148, 512, SMEM_TOT>>>(
        x, lens, Wihf, Whhf, bihf, bhhf, Wihb, Whhb, bihb, bhhb, out);
}